// round 7
// baseline (speedup 1.0000x reference)
#include <cuda_runtime.h>
#include <cuda_fp16.h>
#include <math.h>
#include <stdint.h>

#define NP 16384
#define NR 8192
#define GRIDN 13
#define NCELL (GRIDN*GRIDN*GRIDN)
#define CAP 64
#define RADIUS2 (0.075f*0.075f)

// ---------------- static scratch ----------------
__device__ int    d_cellCnt[NCELL];
__device__ float4 d_cellPts[NCELL*CAP];
__device__ int    d_nbr[NP*3];
__device__ unsigned short d_rgbt[NR*128];    // rgb features point-major fp16
__device__ unsigned short d_maxf[NP*128];    // max-pooled neighbor features
__device__ unsigned short d_hw[382976];      // all weights fp16, k-major
__device__ float  d_bns[5*384];
__device__ float  d_bnt[5*384];

// ---------------- PTX helpers ----------------
__device__ __forceinline__ uint32_t smem_u32(const void* p) {
    uint32_t a;
    asm("{ .reg .u64 t; cvta.to.shared.u64 t, %1; cvt.u32.u64 %0, t; }" : "=r"(a) : "l"(p));
    return a;
}
__device__ __forceinline__ void cpasync16(uint32_t s, const void* g) {
    asm volatile("cp.async.cg.shared.global [%0], [%1], 16;" :: "r"(s), "l"(g));
}
#define CP_COMMIT() asm volatile("cp.async.commit_group;")
#define LDSM4(r0,r1,r2,r3,a) \
    asm volatile("ldmatrix.sync.aligned.m8n8.x4.shared.b16 {%0,%1,%2,%3},[%4];" \
        : "=r"(r0),"=r"(r1),"=r"(r2),"=r"(r3) : "r"(a))
#define LDSM4T(r0,r1,r2,r3,a) \
    asm volatile("ldmatrix.sync.aligned.m8n8.x4.trans.shared.b16 {%0,%1,%2,%3},[%4];" \
        : "=r"(r0),"=r"(r1),"=r"(r2),"=r"(r3) : "r"(a))
__device__ __forceinline__ void mma16(float* c, const uint32_t* a, uint32_t b0, uint32_t b1) {
    asm volatile(
        "mma.sync.aligned.m16n8k16.row.col.f32.f16.f16.f32 "
        "{%0,%1,%2,%3},{%4,%5,%6,%7},{%8,%9},{%0,%1,%2,%3};"
        : "+f"(c[0]), "+f"(c[1]), "+f"(c[2]), "+f"(c[3])
        : "r"(a[0]), "r"(a[1]), "r"(a[2]), "r"(a[3]), "r"(b0), "r"(b1));
}

// ---------------- spatial grid + 3NN ----------------
__global__ void k_clear() {
    int i = blockIdx.x*blockDim.x + threadIdx.x;
    if (i < NCELL) d_cellCnt[i] = 0;
}
__device__ __forceinline__ int cidx(float v) {
    int c = (int)(v * (float)GRIDN);
    return c < 0 ? 0 : (c > GRIDN-1 ? GRIDN-1 : c);
}
__global__ void k_build(const float* __restrict__ rgb) {
    int i = blockIdx.x*blockDim.x + threadIdx.x;
    if (i >= NR) return;
    float x = rgb[3*i], y = rgb[3*i+1], z = rgb[3*i+2];
    int c = (cidx(x)*GRIDN + cidx(y))*GRIDN + cidx(z);
    int p = atomicAdd(&d_cellCnt[c], 1);
    if (p < CAP) d_cellPts[c*CAP + p] = make_float4(x, y, z, __int_as_float(i));
}
__global__ void k_3nn(const float* __restrict__ pcd) {
    int i = blockIdx.x*blockDim.x + threadIdx.x;
    if (i >= NP) return;
    float x = pcd[3*i], y = pcd[3*i+1], z = pcd[3*i+2];
    int cx = cidx(x), cy = cidx(y), cz = cidx(z);
    int x0 = max(cx-1,0), x1 = min(cx+1,GRIDN-1);
    int y0 = max(cy-1,0), y1 = min(cy+1,GRIDN-1);
    int z0 = max(cz-1,0), z1 = min(cz+1,GRIDN-1);
    float b0 = 3.4e38f, b1 = 3.4e38f, b2 = 3.4e38f;
    int   i0 = NR, i1 = NR, i2 = NR;
    for (int ax = x0; ax <= x1; ax++)
    for (int ay = y0; ay <= y1; ay++)
    for (int az = z0; az <= z1; az++) {
        int c = (ax*GRIDN + ay)*GRIDN + az;
        int cnt = min(d_cellCnt[c], CAP);
        const float4* pts = &d_cellPts[c*CAP];
        for (int p = 0; p < cnt; p++) {
            float4 q = pts[p];
            float dx = x - q.x, dy = y - q.y, dz = z - q.z;
            float d = fmaf(dx, dx, fmaf(dy, dy, dz*dz));
            if (d <= RADIUS2 && d < b2) {
                int qi = __float_as_int(q.w);
                if (d < b0)      { b2=b1;i2=i1; b1=b0;i1=i0; b0=d;i0=qi; }
                else if (d < b1) { b2=b1;i2=i1; b1=d; i1=qi; }
                else             { b2=d; i2=qi; }
            }
        }
    }
    d_nbr[3*i] = i0; d_nbr[3*i+1] = i1; d_nbr[3*i+2] = i2;
}

// ---------------- rgb features: ch-major fp32 -> point-major fp16 ----------------
__global__ void k_trans16(const float* __restrict__ in) {
    __shared__ float t[32][33];
    int nb = blockIdx.x * 32;
    int cb = blockIdx.y * 32;
    int tx = threadIdx.x, ty = threadIdx.y;
    #pragma unroll
    for (int i = 0; i < 32; i += 8)
        t[ty+i][tx] = in[(size_t)(cb + ty + i)*NR + nb + tx];
    __syncthreads();
    #pragma unroll
    for (int i = 0; i < 32; i += 8)
        d_rgbt[(size_t)(nb + ty + i)*128 + cb + tx] =
            __half_as_ushort(__float2half(t[tx][ty+i]));
}

// ---------------- fold BN ----------------
__global__ void k_bnprep5(const float* b0, const float* b1, const float* b2,
                          const float* b3, const float* b4) {
    const int Cs[5] = {384, 256, 160, 160, 128};
    const float* ps[5] = {b0, b1, b2, b3, b4};
    int slot = blockIdx.x;
    const float* bn = ps[slot];
    int C = Cs[slot];
    for (int c = threadIdx.x; c < C; c += blockDim.x) {
        float g = bn[c], b = bn[C+c], m = bn[2*C+c], v = bn[3*C+c];
        float s = g * rsqrtf(v + 1e-5f);
        d_bns[slot*384 + c] = s;
        d_bnt[slot*384 + c] = b - m*s;
    }
}

// ---------------- weight convert fp32[M][K] -> fp16[K][M] ----------------
struct WSegs { const float* s[8]; int M[8]; int K[8]; int off[8]; };
__global__ void k_wcvt(WSegs ws) {
    int t = blockIdx.x*blockDim.x + threadIdx.x;
    #pragma unroll
    for (int i = 0; i < 8; i++) {
        int sz = ws.M[i] * ws.K[i];
        if (t < sz) {
            int m = t / ws.K[i], k = t % ws.K[i];
            d_hw[ws.off[i] + (size_t)k * ws.M[i] + m] = __half_as_ushort(__float2half(ws.s[i][t]));
            return;
        }
        t -= sz;
    }
}

// ---------------- mega kernel: gather + full GEMM chain + heads ----------------
#define ASTR 392
#define ABYTES (128*ASTR*2)            // 100352
#define WSTR 136
#define WCH (32*WSTR*2)                // 8704
#define SMEM_MEGA (2*ABYTES + 3*WCH)   // 226816

struct LBias { const float* b[8]; };

__global__ void __launch_bounds__(256, 1)
k_mega(const float* __restrict__ pcdf, const __half* __restrict__ Wg, LBias bias,
       const float* __restrict__ sh2w, const float* __restrict__ sh2b,
       float* __restrict__ outScore, float* __restrict__ outVf)
{
    extern __shared__ __align__(16) unsigned char smem[];
    const uint32_t sbase = smem_u32(smem);
    const int tid = threadIdx.x, wid = tid >> 5, lane = tid & 31;
    const int warp_m = wid & 3, warp_n = wid >> 2;
    const int li = lane & 15, h8 = (lane >> 4) << 3;
    const int rowbase = blockIdx.x * 128;

    // ---- gather: xcat -> A(0..383), maxf -> global ----
    #pragma unroll 4
    for (int i = 0; i < 16; i++) {
        int p = wid*16 + i;
        int ptg = rowbase + p;
        int n0 = d_nbr[3*ptg], n1 = d_nbr[3*ptg+1], n2 = d_nbr[3*ptg+2];
        uint2 z = make_uint2(0u, 0u);
        uint2 u0 = (n0 < NR) ? *(const uint2*)&d_rgbt[(size_t)n0*128 + lane*4] : z;
        uint2 u1 = (n1 < NR) ? *(const uint2*)&d_rgbt[(size_t)n1*128 + lane*4] : z;
        uint2 u2 = (n2 < NR) ? *(const uint2*)&d_rgbt[(size_t)n2*128 + lane*4] : z;
        unsigned char* arow = smem + (size_t)(p*ASTR + lane*4)*2;
        *(uint2*)(arow)       = u0;
        *(uint2*)(arow + 256) = u1;
        *(uint2*)(arow + 512) = u2;
        __half2 a0 = *(__half2*)&u0.x, a1 = *(__half2*)&u0.y;
        __half2 b0 = *(__half2*)&u1.x, b1 = *(__half2*)&u1.y;
        __half2 c0 = *(__half2*)&u2.x, c1 = *(__half2*)&u2.y;
        __half2 m0 = __hmax2(__hmax2(a0, b0), c0);
        __half2 m1 = __hmax2(__hmax2(a1, b1), c1);
        uint2 mu; mu.x = *(uint32_t*)&m0; mu.y = *(uint32_t*)&m1;
        *(uint2*)&d_maxf[(size_t)ptg*128 + lane*4] = mu;
    }
    __syncthreads();

    const int Ks[8]   = {384,384,256,256,160,160,160,128};
    const int Ms[8]   = {384,128,256,128,160,160,128,128};
    const int dco[8]  = {0,0,0,32,0,0,0,0};
    const int slot[8] = {0,-1,1,-1,2,3,-1,4};
    const int woff[8] = {0,147456,196608,262144,294912,320512,346112,366592};
    const uint32_t Wb = sbase + 2*ABYTES;

    for (int l = 0; l < 8; l++) {
        if (l == 1) {           // maxf -> A cols 128..255 (uint4 = 8 halves per slot)
            for (int t = tid; t < 2048; t += 256) {
                int p = t >> 4, q = t & 15;
                *(uint4*)(smem + (size_t)(p*ASTR + 128 + q*8)*2) =
                    *(const uint4*)&d_maxf[(size_t)(rowbase+p)*128 + q*8];
            }
            __syncthreads();
        }
        if (l == 3) {           // pcd features -> A cols 0..31
            __half* ah = (__half*)smem;
            for (int t = tid; t < 1024; t += 256) {
                int ch = t >> 5, j = t & 31;
                float4 v = *(const float4*)&pcdf[(size_t)ch*NP + rowbase + j*4];
                ah[(j*4+0)*ASTR + ch] = __float2half(v.x);
                ah[(j*4+1)*ASTR + ch] = __float2half(v.y);
                ah[(j*4+2)*ASTR + ch] = __float2half(v.z);
                ah[(j*4+3)*ASTR + ch] = __float2half(v.w);
            }
            __syncthreads();
        }

        const uint32_t srcA = sbase + ((l & 1) ? ABYTES : 0);
        unsigned char* dstP = smem + ((l & 1) ? 0 : ABYTES);
        const int K = Ks[l], M = Ms[l];
        const int NKC = K >> 5;
        const __half* W = Wg + woff[l];
        const float* bi = bias.b[l];
        const int sl = slot[l];
        const float* sc = (sl >= 0) ? d_bns + sl*384 : nullptr;
        const float* sh = (sl >= 0) ? d_bnt + sl*384 : nullptr;

        for (int mc = 0; mc < M; mc += 128) {
            const int ncols = min(128, M - mc);
            const int nf = ncols >> 3;   // 16 or 4
            float acc[2][8][4];
            #pragma unroll
            for (int i = 0; i < 2; i++)
                #pragma unroll
                for (int j = 0; j < 8; j++)
                    #pragma unroll
                    for (int q = 0; q < 4; q++) acc[i][j][q] = 0.f;

            auto issueW = [&](int c) {
                uint32_t stg = Wb + (c % 3) * WCH;
                int tot = 32 * nf;
                for (int t = tid; t < tot; t += 256) {
                    int kr = t / nf, qn = t % nf;
                    cpasync16(stg + (kr*WSTR + qn*8)*2,
                              W + (size_t)(c*32 + kr)*M + mc + qn*8);
                }
                CP_COMMIT();
            };

            int issued = 1;
            issueW(0);
            if (NKC > 1) { issueW(1); issued = 2; }

            for (int c = 0; c < NKC; c++) {
                if (issued < NKC) { issueW(issued); issued++; }
                int pending = issued - c - 1;
                if (pending >= 2)      asm volatile("cp.async.wait_group 2;");
                else if (pending == 1) asm volatile("cp.async.wait_group 1;");
                else                   asm volatile("cp.async.wait_group 0;");
                __syncthreads();
                uint32_t Ws = Wb + (c % 3) * WCH;
                #pragma unroll
                for (int kk = 0; kk < 32; kk += 16) {
                    uint32_t a[2][4];
                    #pragma unroll
                    for (int mt = 0; mt < 2; mt++) {
                        uint32_t ad = srcA +
                            ((uint32_t)(warp_m*32 + mt*16 + li)*ASTR + c*32 + kk + h8)*2;
                        LDSM4(a[mt][0], a[mt][1], a[mt][2], a[mt][3], ad);
                    }
                    uint32_t b[4][4];
                    #pragma unroll
                    for (int nt2 = 0; nt2 < 4; nt2++) {
                        uint32_t bd = Ws + ((kk + li)*WSTR + warp_n*64 + nt2*16 + h8)*2;
                        LDSM4T(b[nt2][0], b[nt2][1], b[nt2][2], b[nt2][3], bd);
                    }
                    #pragma unroll
                    for (int mt = 0; mt < 2; mt++)
                        #pragma unroll
                        for (int nt = 0; nt < 8; nt++)
                            mma16(acc[mt][nt], a[mt], b[nt>>1][(nt&1)*2], b[nt>>1][(nt&1)*2+1]);
                }
                __syncthreads();
            }

            // epilogue -> dst SMEM buffer
            const int g = lane >> 2, tp = (lane & 3) * 2;
            #pragma unroll
            for (int nt = 0; nt < 8; nt++) {
                int lc = warp_n*64 + nt*8;
                if (lc >= ncols) break;
                int m = mc + lc + tp;
                float bi0 = __ldg(&bi[m]), bi1 = __ldg(&bi[m+1]);
                float s0 = 0.f, s1 = 0.f, t0 = 0.f, t1 = 0.f;
                if (sl >= 0) {
                    s0 = __ldg(&sc[m]); s1 = __ldg(&sc[m+1]);
                    t0 = __ldg(&sh[m]); t1 = __ldg(&sh[m+1]);
                }
                #pragma unroll
                for (int mt = 0; mt < 2; mt++) {
                    #pragma unroll
                    for (int h = 0; h < 2; h++) {
                        int pt = warp_m*32 + mt*16 + h*8 + g;
                        float x0 = acc[mt][nt][2*h]   + bi0;
                        float x1 = acc[mt][nt][2*h+1] + bi1;
                        if (sl >= 0) {
                            x0 = fmaxf(fmaf(x0, s0, t0), 0.f);
                            x1 = fmaxf(fmaf(x1, s1, t1), 0.f);
                        }
                        *(__half2*)(dstP + (size_t)(pt*ASTR + dco[l] + m)*2) =
                            __floats2half2_rn(x0, x1);
                    }
                }
            }
        }
        __syncthreads();
    }

    // ---- heads: s in A, fp in B ----
    const unsigned char* sA = smem;
    const unsigned char* sB = smem + ABYTES;
    float4 wv = *(const float4*)&sh2w[lane*4];
    float sb = __ldg(sh2b);
    #pragma unroll 4
    for (int i = 0; i < 16; i++) {
        int p = wid*16 + i, ptg = rowbase + p;
        uint2 su = *(const uint2*)(sA + (size_t)(p*ASTR + lane*4)*2);
        __half2 s0 = *(__half2*)&su.x, s1 = *(__half2*)&su.y;
        float sacc = __low2float(s0)*wv.x + __high2float(s0)*wv.y
                   + __low2float(s1)*wv.z + __high2float(s1)*wv.w;
        uint2 fu = *(const uint2*)(sB + (size_t)(p*ASTR + lane*4)*2);
        __half2 f0 = *(__half2*)&fu.x, f1 = *(__half2*)&fu.y;
        float v0 = __low2float(f0), v1 = __high2float(f0);
        float v2 = __low2float(f1), v3 = __high2float(f1);
        float ss = v0*v0 + v1*v1 + v2*v2 + v3*v3;
        #pragma unroll
        for (int o = 16; o > 0; o >>= 1) {
            sacc += __shfl_xor_sync(0xffffffff, sacc, o);
            ss   += __shfl_xor_sync(0xffffffff, ss, o);
        }
        if (lane == 0) outScore[ptg] = 1.f / (1.f + expf(-(sacc + sb)));
        float inv = 1.f / fmaxf(sqrtf(ss), 1e-12f);
        *(float4*)&outVf[(size_t)ptg*128 + lane*4] =
            make_float4(v0*inv, v1*inv, v2*inv, v3*inv);
    }
}

extern "C" void kernel_launch(void* const* d_in, const int* in_sizes, int n_in,
                              void* d_out, int out_size) {
    const float* pcd_xyz = (const float*)d_in[0];
    const float* rgb_xyz = (const float*)d_in[1];
    const float* pcd_f   = (const float*)d_in[2];
    const float* rgb_f   = (const float*)d_in[3];
    const float* cc1_w = (const float*)d_in[4];  const float* cc1_b = (const float*)d_in[5];
    const float* cc_bn = (const float*)d_in[6];
    const float* cc2_w = (const float*)d_in[7];  const float* cc2_b = (const float*)d_in[8];
    const float* co1_w = (const float*)d_in[9];  const float* co1_b = (const float*)d_in[10];
    const float* co_bn = (const float*)d_in[11];
    const float* co2_w = (const float*)d_in[12]; const float* co2_b = (const float*)d_in[13];
    const float* dh1_w = (const float*)d_in[14]; const float* dh1_b = (const float*)d_in[15];
    const float* dh1_bn= (const float*)d_in[16];
    const float* dh2_w = (const float*)d_in[17]; const float* dh2_b = (const float*)d_in[18];
    const float* dh2_bn= (const float*)d_in[19];
    const float* dh3_w = (const float*)d_in[20]; const float* dh3_b = (const float*)d_in[21];
    const float* sh1_w = (const float*)d_in[22]; const float* sh1_b = (const float*)d_in[23];
    const float* sh_bn = (const float*)d_in[24];
    const float* sh2_w = (const float*)d_in[25]; const float* sh2_b = (const float*)d_in[26];
    float* out = (float*)d_out;

    unsigned short* hw;
    cudaGetSymbolAddress((void**)&hw, d_hw);
    cudaFuncSetAttribute(k_mega, cudaFuncAttributeMaxDynamicSharedMemorySize, SMEM_MEGA);

    WSegs ws;
    const float* srcs[8] = {cc1_w, cc2_w, co1_w, co2_w, dh1_w, dh2_w, dh3_w, sh1_w};
    int Ms[8]   = {384, 128, 256, 128, 160, 160, 128, 128};
    int Ks[8]   = {384, 384, 256, 256, 160, 160, 160, 128};
    int offs[8] = {0, 147456, 196608, 262144, 294912, 320512, 346112, 366592};
    for (int i = 0; i < 8; i++) { ws.s[i] = srcs[i]; ws.M[i] = Ms[i]; ws.K[i] = Ks[i]; ws.off[i] = offs[i]; }

    LBias lb;
    lb.b[0] = cc1_b; lb.b[1] = cc2_b; lb.b[2] = co1_b; lb.b[3] = co2_b;
    lb.b[4] = dh1_b; lb.b[5] = dh2_b; lb.b[6] = dh3_b; lb.b[7] = sh1_b;

    // ---- prep ----
    k_clear<<<(NCELL+255)/256, 256>>>();
    k_build<<<(NR+255)/256, 256>>>(rgb_xyz);
    k_3nn<<<(NP+127)/128, 128>>>(pcd_xyz);
    k_trans16<<<dim3(NR/32, 4), dim3(32,8)>>>(rgb_f);
    k_bnprep5<<<5, 384>>>(cc_bn, co_bn, dh1_bn, dh2_bn, sh_bn);
    k_wcvt<<<(382976+255)/256, 256>>>(ws);
    cudaMemcpyAsync(out, pcd_xyz, (size_t)NP*3*sizeof(float), cudaMemcpyDeviceToDevice);

    // ---- fused chain ----
    k_mega<<<128, 256, SMEM_MEGA>>>(pcd_f, (const __half*)hw, lb,
                                    sh2_w, sh2_b,
                                    out + (size_t)NP*3, out + (size_t)NP*4);
}

// round 9
// speedup vs baseline: 1.0128x; 1.0128x over previous
#include <cuda_runtime.h>
#include <cuda_fp16.h>
#include <math.h>
#include <stdint.h>

#define NP 16384
#define NR 8192
#define GRIDN 13
#define NCELL (GRIDN*GRIDN*GRIDN)
#define CAP 64
#define RADIUS2 (0.075f*0.075f)

// ---------------- static scratch ----------------
__device__ int    d_cellCnt[NCELL];
__device__ float4 d_cellPts[NCELL*CAP];
__device__ int    d_nbr[NP*3];
__device__ unsigned short d_rgbt[NR*128];    // rgb features point-major fp16
__device__ unsigned short d_maxf[NP*128];    // max-pooled neighbor features
__device__ unsigned short d_hw[382976];      // all weights fp16, k-major
__device__ float  d_bns[5*384];
__device__ float  d_bnt[5*384];

// ---------------- PTX helpers ----------------
__device__ __forceinline__ uint32_t smem_u32(const void* p) {
    uint32_t a;
    asm("{ .reg .u64 t; cvta.to.shared.u64 t, %1; cvt.u32.u64 %0, t; }" : "=r"(a) : "l"(p));
    return a;
}
__device__ __forceinline__ void cpasync16(uint32_t s, const void* g) {
    asm volatile("cp.async.cg.shared.global [%0], [%1], 16;" :: "r"(s), "l"(g));
}
#define CP_COMMIT() asm volatile("cp.async.commit_group;")
#define LDSM4(r0,r1,r2,r3,a) \
    asm volatile("ldmatrix.sync.aligned.m8n8.x4.shared.b16 {%0,%1,%2,%3},[%4];" \
        : "=r"(r0),"=r"(r1),"=r"(r2),"=r"(r3) : "r"(a))
#define LDSM4T(r0,r1,r2,r3,a) \
    asm volatile("ldmatrix.sync.aligned.m8n8.x4.trans.shared.b16 {%0,%1,%2,%3},[%4];" \
        : "=r"(r0),"=r"(r1),"=r"(r2),"=r"(r3) : "r"(a))
__device__ __forceinline__ void mma16(float* c, const uint32_t* a, uint32_t b0, uint32_t b1) {
    asm volatile(
        "mma.sync.aligned.m16n8k16.row.col.f32.f16.f16.f32 "
        "{%0,%1,%2,%3},{%4,%5,%6,%7},{%8,%9},{%0,%1,%2,%3};"
        : "+f"(c[0]), "+f"(c[1]), "+f"(c[2]), "+f"(c[3])
        : "r"(a[0]), "r"(a[1]), "r"(a[2]), "r"(a[3]), "r"(b0), "r"(b1));
}

// ---------------- spatial grid + 3NN ----------------
__global__ void k_clear() {
    int i = blockIdx.x*blockDim.x + threadIdx.x;
    if (i < NCELL) d_cellCnt[i] = 0;
}
__device__ __forceinline__ int cidx(float v) {
    int c = (int)(v * (float)GRIDN);
    return c < 0 ? 0 : (c > GRIDN-1 ? GRIDN-1 : c);
}
__global__ void k_build(const float* __restrict__ rgb) {
    int i = blockIdx.x*blockDim.x + threadIdx.x;
    if (i >= NR) return;
    float x = rgb[3*i], y = rgb[3*i+1], z = rgb[3*i+2];
    int c = (cidx(x)*GRIDN + cidx(y))*GRIDN + cidx(z);
    int p = atomicAdd(&d_cellCnt[c], 1);
    if (p < CAP) d_cellPts[c*CAP + p] = make_float4(x, y, z, __int_as_float(i));
}
__global__ void k_3nn(const float* __restrict__ pcd) {
    int i = blockIdx.x*blockDim.x + threadIdx.x;
    if (i >= NP) return;
    float x = pcd[3*i], y = pcd[3*i+1], z = pcd[3*i+2];
    int cx = cidx(x), cy = cidx(y), cz = cidx(z);
    int x0 = max(cx-1,0), x1 = min(cx+1,GRIDN-1);
    int y0 = max(cy-1,0), y1 = min(cy+1,GRIDN-1);
    int z0 = max(cz-1,0), z1 = min(cz+1,GRIDN-1);
    float b0 = 3.4e38f, b1 = 3.4e38f, b2 = 3.4e38f;
    int   i0 = NR, i1 = NR, i2 = NR;
    for (int ax = x0; ax <= x1; ax++)
    for (int ay = y0; ay <= y1; ay++)
    for (int az = z0; az <= z1; az++) {
        int c = (ax*GRIDN + ay)*GRIDN + az;
        int cnt = min(d_cellCnt[c], CAP);
        const float4* pts = &d_cellPts[c*CAP];
        for (int p = 0; p < cnt; p++) {
            float4 q = pts[p];
            float dx = x - q.x, dy = y - q.y, dz = z - q.z;
            float d = fmaf(dx, dx, fmaf(dy, dy, dz*dz));
            if (d <= RADIUS2 && d < b2) {
                int qi = __float_as_int(q.w);
                if (d < b0)      { b2=b1;i2=i1; b1=b0;i1=i0; b0=d;i0=qi; }
                else if (d < b1) { b2=b1;i2=i1; b1=d; i1=qi; }
                else             { b2=d; i2=qi; }
            }
        }
    }
    d_nbr[3*i] = i0; d_nbr[3*i+1] = i1; d_nbr[3*i+2] = i2;
}

// ---------------- rgb features: ch-major fp32 -> point-major fp16 ----------------
__global__ void k_trans16(const float* __restrict__ in) {
    __shared__ float t[32][33];
    int nb = blockIdx.x * 32;
    int cb = blockIdx.y * 32;
    int tx = threadIdx.x, ty = threadIdx.y;
    #pragma unroll
    for (int i = 0; i < 32; i += 8)
        t[ty+i][tx] = in[(size_t)(cb + ty + i)*NR + nb + tx];
    __syncthreads();
    #pragma unroll
    for (int i = 0; i < 32; i += 8)
        d_rgbt[(size_t)(nb + ty + i)*128 + cb + tx] =
            __half_as_ushort(__float2half(t[tx][ty+i]));
}

// ---------------- fold BN ----------------
__global__ void k_bnprep5(const float* b0, const float* b1, const float* b2,
                          const float* b3, const float* b4) {
    const int Cs[5] = {384, 256, 160, 160, 128};
    const float* ps[5] = {b0, b1, b2, b3, b4};
    int slot = blockIdx.x;
    const float* bn = ps[slot];
    int C = Cs[slot];
    for (int c = threadIdx.x; c < C; c += blockDim.x) {
        float g = bn[c], b = bn[C+c], m = bn[2*C+c], v = bn[3*C+c];
        float s = g * rsqrtf(v + 1e-5f);
        d_bns[slot*384 + c] = s;
        d_bnt[slot*384 + c] = b - m*s;
    }
}

// ---------------- weight convert fp32[M][K] -> fp16[K][M] ----------------
struct WSegs { const float* s[8]; int M[8]; int K[8]; int off[8]; };
__global__ void k_wcvt(WSegs ws) {
    int t = blockIdx.x*blockDim.x + threadIdx.x;
    #pragma unroll
    for (int i = 0; i < 8; i++) {
        int sz = ws.M[i] * ws.K[i];
        if (t < sz) {
            int m = t / ws.K[i], k = t % ws.K[i];
            d_hw[ws.off[i] + (size_t)k * ws.M[i] + m] = __half_as_ushort(__float2half(ws.s[i][t]));
            return;
        }
        t -= sz;
    }
}

// ---------------- mega kernel: gather + full GEMM chain + heads ----------------
#define ASTR 392
#define ABYTES (128*ASTR*2)            // 100352
#define WSTR 136
#define WCH (32*WSTR*2)                // 8704
#define SMEM_MEGA (2*ABYTES + 3*WCH)   // 226816
#define NTH 512

struct LBias { const float* b[8]; };

__global__ void __launch_bounds__(NTH, 1)
k_mega(const float* __restrict__ pcdf, const __half* __restrict__ Wg, LBias bias,
       const float* __restrict__ sh2w, const float* __restrict__ sh2b,
       float* __restrict__ outScore, float* __restrict__ outVf)
{
    extern __shared__ __align__(16) unsigned char smem[];
    const uint32_t sbase = smem_u32(smem);
    const int tid = threadIdx.x, wid = tid >> 5, lane = tid & 31;
    const int warp_m = wid & 7, warp_n = wid >> 3;   // 8 x 2 warps
    const int li = lane & 15, h8 = (lane >> 4) << 3;
    const int rowbase = blockIdx.x * 128;

    // ---- gather: xcat -> A(0..383), maxf -> global (8 points per warp) ----
    #pragma unroll
    for (int i = 0; i < 8; i++) {
        int p = wid*8 + i;
        int ptg = rowbase + p;
        int n0 = d_nbr[3*ptg], n1 = d_nbr[3*ptg+1], n2 = d_nbr[3*ptg+2];
        uint2 z = make_uint2(0u, 0u);
        uint2 u0 = (n0 < NR) ? *(const uint2*)&d_rgbt[(size_t)n0*128 + lane*4] : z;
        uint2 u1 = (n1 < NR) ? *(const uint2*)&d_rgbt[(size_t)n1*128 + lane*4] : z;
        uint2 u2 = (n2 < NR) ? *(const uint2*)&d_rgbt[(size_t)n2*128 + lane*4] : z;
        unsigned char* arow = smem + (size_t)(p*ASTR + lane*4)*2;
        *(uint2*)(arow)       = u0;
        *(uint2*)(arow + 256) = u1;
        *(uint2*)(arow + 512) = u2;
        __half2 a0 = *(__half2*)&u0.x, a1 = *(__half2*)&u0.y;
        __half2 b0 = *(__half2*)&u1.x, b1 = *(__half2*)&u1.y;
        __half2 c0 = *(__half2*)&u2.x, c1 = *(__half2*)&u2.y;
        __half2 m0 = __hmax2(__hmax2(a0, b0), c0);
        __half2 m1 = __hmax2(__hmax2(a1, b1), c1);
        uint2 mu; mu.x = *(uint32_t*)&m0; mu.y = *(uint32_t*)&m1;
        *(uint2*)&d_maxf[(size_t)ptg*128 + lane*4] = mu;
    }
    __syncthreads();

    const int Ks[8]   = {384,384,256,256,160,160,160,128};
    const int Ms[8]   = {384,128,256,128,160,160,128,128};
    const int dco[8]  = {0,0,0,32,0,0,0,0};
    const int slot[8] = {0,-1,1,-1,2,3,-1,4};
    const int woff[8] = {0,147456,196608,262144,294912,320512,346112,366592};
    const uint32_t Wb = sbase + 2*ABYTES;

    for (int l = 0; l < 8; l++) {
        if (l == 1) {           // maxf -> A cols 128..255 (uint4 = 8 halves per slot)
            for (int t = tid; t < 2048; t += NTH) {
                int p = t >> 4, q = t & 15;
                *(uint4*)(smem + (size_t)(p*ASTR + 128 + q*8)*2) =
                    *(const uint4*)&d_maxf[(size_t)(rowbase+p)*128 + q*8];
            }
            __syncthreads();
        }
        if (l == 3) {           // pcd features -> A cols 0..31
            __half* ah = (__half*)smem;
            for (int t = tid; t < 1024; t += NTH) {
                int ch = t >> 5, j = t & 31;
                float4 v = *(const float4*)&pcdf[(size_t)ch*NP + rowbase + j*4];
                ah[(j*4+0)*ASTR + ch] = __float2half(v.x);
                ah[(j*4+1)*ASTR + ch] = __float2half(v.y);
                ah[(j*4+2)*ASTR + ch] = __float2half(v.z);
                ah[(j*4+3)*ASTR + ch] = __float2half(v.w);
            }
            __syncthreads();
        }

        const uint32_t srcA = sbase + ((l & 1) ? ABYTES : 0);
        unsigned char* dstP = smem + ((l & 1) ? 0 : ABYTES);
        const int K = Ks[l], M = Ms[l];
        const int NKC = K >> 5;
        const __half* W = Wg + woff[l];
        const float* bi = bias.b[l];
        const int sl = slot[l];
        const float* sc = (sl >= 0) ? d_bns + sl*384 : nullptr;
        const float* sh = (sl >= 0) ? d_bnt + sl*384 : nullptr;

        for (int mc = 0; mc < M; mc += 128) {
            const int ncols = min(128, M - mc);
            const int nf = ncols >> 3;   // 16 or 4
            float acc[8][4];
            #pragma unroll
            for (int j = 0; j < 8; j++)
                #pragma unroll
                for (int q = 0; q < 4; q++) acc[j][q] = 0.f;

            auto issueW = [&](int c) {
                uint32_t stg = Wb + (c % 3) * WCH;
                int tot = 32 * nf;
                for (int t = tid; t < tot; t += NTH) {
                    int kr = t / nf, qn = t % nf;
                    cpasync16(stg + (kr*WSTR + qn*8)*2,
                              W + (size_t)(c*32 + kr)*M + mc + qn*8);
                }
                CP_COMMIT();
            };

            int issued = 1;
            issueW(0);
            if (NKC > 1) { issueW(1); issued = 2; }

            for (int c = 0; c < NKC; c++) {
                if (issued < NKC) { issueW(issued); issued++; }
                int pending = issued - c - 1;
                if (pending >= 2)      asm volatile("cp.async.wait_group 2;");
                else if (pending == 1) asm volatile("cp.async.wait_group 1;");
                else                   asm volatile("cp.async.wait_group 0;");
                __syncthreads();
                uint32_t Ws = Wb + (c % 3) * WCH;
                #pragma unroll
                for (int kk = 0; kk < 32; kk += 16) {
                    uint32_t a[4];
                    {
                        uint32_t ad = srcA +
                            ((uint32_t)(warp_m*16 + li)*ASTR + c*32 + kk + h8)*2;
                        LDSM4(a[0], a[1], a[2], a[3], ad);
                    }
                    uint32_t b[4][4];
                    #pragma unroll
                    for (int nt2 = 0; nt2 < 4; nt2++) {
                        uint32_t bd = Ws + ((kk + li)*WSTR + warp_n*64 + nt2*16 + h8)*2;
                        LDSM4T(b[nt2][0], b[nt2][1], b[nt2][2], b[nt2][3], bd);
                    }
                    #pragma unroll
                    for (int nt = 0; nt < 8; nt++)
                        mma16(acc[nt], a, b[nt>>1][(nt&1)*2], b[nt>>1][(nt&1)*2+1]);
                }
                __syncthreads();
            }

            // epilogue -> dst SMEM buffer (warp tile: 16 pts x 64 ch)
            const int g = lane >> 2, tp = (lane & 3) * 2;
            #pragma unroll
            for (int nt = 0; nt < 8; nt++) {
                int lc = warp_n*64 + nt*8;
                if (lc >= ncols) break;
                int m = mc + lc + tp;
                float bi0 = __ldg(&bi[m]), bi1 = __ldg(&bi[m+1]);
                float s0 = 0.f, s1 = 0.f, t0 = 0.f, t1 = 0.f;
                if (sl >= 0) {
                    s0 = __ldg(&sc[m]); s1 = __ldg(&sc[m+1]);
                    t0 = __ldg(&sh[m]); t1 = __ldg(&sh[m+1]);
                }
                #pragma unroll
                for (int h = 0; h < 2; h++) {
                    int pt = warp_m*16 + h*8 + g;
                    float x0 = acc[nt][2*h]   + bi0;
                    float x1 = acc[nt][2*h+1] + bi1;
                    if (sl >= 0) {
                        x0 = fmaxf(fmaf(x0, s0, t0), 0.f);
                        x1 = fmaxf(fmaf(x1, s1, t1), 0.f);
                    }
                    *(__half2*)(dstP + (size_t)(pt*ASTR + dco[l] + m)*2) =
                        __floats2half2_rn(x0, x1);
                }
            }
        }
        __syncthreads();
    }

    // ---- heads: s in A, fp in B (8 points per warp) ----
    const unsigned char* sA = smem;
    const unsigned char* sB = smem + ABYTES;
    float4 wv = *(const float4*)&sh2w[lane*4];
    float sb = __ldg(sh2b);
    #pragma unroll
    for (int i = 0; i < 8; i++) {
        int p = wid*8 + i, ptg = rowbase + p;
        uint2 su = *(const uint2*)(sA + (size_t)(p*ASTR + lane*4)*2);
        __half2 s0 = *(__half2*)&su.x, s1 = *(__half2*)&su.y;
        float sacc = __low2float(s0)*wv.x + __high2float(s0)*wv.y
                   + __low2float(s1)*wv.z + __high2float(s1)*wv.w;
        uint2 fu = *(const uint2*)(sB + (size_t)(p*ASTR + lane*4)*2);
        __half2 f0 = *(__half2*)&fu.x, f1 = *(__half2*)&fu.y;
        float v0 = __low2float(f0), v1 = __high2float(f0);
        float v2 = __low2float(f1), v3 = __high2float(f1);
        float ss = v0*v0 + v1*v1 + v2*v2 + v3*v3;
        #pragma unroll
        for (int o = 16; o > 0; o >>= 1) {
            sacc += __shfl_xor_sync(0xffffffff, sacc, o);
            ss   += __shfl_xor_sync(0xffffffff, ss, o);
        }
        if (lane == 0) outScore[ptg] = 1.f / (1.f + expf(-(sacc + sb)));
        float inv = 1.f / fmaxf(sqrtf(ss), 1e-12f);
        *(float4*)&outVf[(size_t)ptg*128 + lane*4] =
            make_float4(v0*inv, v1*inv, v2*inv, v3*inv);
    }
}

extern "C" void kernel_launch(void* const* d_in, const int* in_sizes, int n_in,
                              void* d_out, int out_size) {
    const float* pcd_xyz = (const float*)d_in[0];
    const float* rgb_xyz = (const float*)d_in[1];
    const float* pcd_f   = (const float*)d_in[2];
    const float* rgb_f   = (const float*)d_in[3];
    const float* cc1_w = (const float*)d_in[4];  const float* cc1_b = (const float*)d_in[5];
    const float* cc_bn = (const float*)d_in[6];
    const float* cc2_w = (const float*)d_in[7];  const float* cc2_b = (const float*)d_in[8];
    const float* co1_w = (const float*)d_in[9];  const float* co1_b = (const float*)d_in[10];
    const float* co_bn = (const float*)d_in[11];
    const float* co2_w = (const float*)d_in[12]; const float* co2_b = (const float*)d_in[13];
    const float* dh1_w = (const float*)d_in[14]; const float* dh1_b = (const float*)d_in[15];
    const float* dh1_bn= (const float*)d_in[16];
    const float* dh2_w = (const float*)d_in[17]; const float* dh2_b = (const float*)d_in[18];
    const float* dh2_bn= (const float*)d_in[19];
    const float* dh3_w = (const float*)d_in[20]; const float* dh3_b = (const float*)d_in[21];
    const float* sh1_w = (const float*)d_in[22]; const float* sh1_b = (const float*)d_in[23];
    const float* sh_bn = (const float*)d_in[24];
    const float* sh2_w = (const float*)d_in[25]; const float* sh2_b = (const float*)d_in[26];
    float* out = (float*)d_out;

    unsigned short* hw;
    cudaGetSymbolAddress((void**)&hw, d_hw);
    cudaFuncSetAttribute(k_mega, cudaFuncAttributeMaxDynamicSharedMemorySize, SMEM_MEGA);

    WSegs ws;
    const float* srcs[8] = {cc1_w, cc2_w, co1_w, co2_w, dh1_w, dh2_w, dh3_w, sh1_w};
    int Ms[8]   = {384, 128, 256, 128, 160, 160, 128, 128};
    int Ks[8]   = {384, 384, 256, 256, 160, 160, 160, 128};
    int offs[8] = {0, 147456, 196608, 262144, 294912, 320512, 346112, 366592};
    for (int i = 0; i < 8; i++) { ws.s[i] = srcs[i]; ws.M[i] = Ms[i]; ws.K[i] = Ks[i]; ws.off[i] = offs[i]; }

    LBias lb;
    lb.b[0] = cc1_b; lb.b[1] = cc2_b; lb.b[2] = co1_b; lb.b[3] = co2_b;
    lb.b[4] = dh1_b; lb.b[5] = dh2_b; lb.b[6] = dh3_b; lb.b[7] = sh1_b;

    // ---- prep ----
    k_clear<<<(NCELL+255)/256, 256>>>();
    k_build<<<(NR+255)/256, 256>>>(rgb_xyz);
    k_3nn<<<(NP+127)/128, 128>>>(pcd_xyz);
    k_trans16<<<dim3(NR/32, 4), dim3(32,8)>>>(rgb_f);
    k_bnprep5<<<5, 384>>>(cc_bn, co_bn, dh1_bn, dh2_bn, sh_bn);
    k_wcvt<<<(382976+255)/256, 256>>>(ws);
    cudaMemcpyAsync(out, pcd_xyz, (size_t)NP*3*sizeof(float), cudaMemcpyDeviceToDevice);

    // ---- fused chain ----
    k_mega<<<128, NTH, SMEM_MEGA>>>(pcd_f, (const __half*)hw, lb,
                                    sh2_w, sh2_b,
                                    out + (size_t)NP*3, out + (size_t)NP*4);
}